// round 8
// baseline (speedup 1.0000x reference)
#include <cuda_runtime.h>
#include <cstddef>

// Problem constants (bigram trie, fixed shapes from reference)
#define V_  32768
#define C_  32
#define B_  32
#define K_  (V_ * C_)        // 1048576 bigram nodes
#define X_  (K_ + 1)         // pointers length
#define G_  V_               // unigram count
#define U_  (V_ + 1)         // first bigram node index

// Fused fill + sparse override.
// Grid: 1024 blocks (32 rows x 32 chunks of 1024 v's), 256 threads, float4/thread.
// Phase 1: out[b, v] = logs[X+G+h_b] + logs[v]   (streaming, coalesced)
//          Override operands (pointers/ids/logs[node]) are prefetched here,
//          BEFORE the barrier, so their latency overlaps the fill.
// Phase 2: threads 0..31 apply the (avg 1 per block) overrides with a single
//          predicated scalar store.
__global__ void __launch_bounds__(256) llm_fused_kernel(
    const int* __restrict__ hist,
    const int* __restrict__ idx,
    const int* __restrict__ pointers,
    const int* __restrict__ ids,
    const float* __restrict__ logs,
    float* __restrict__ out)
{
    const int blk   = blockIdx.x;          // 0..1023
    const int b     = blk >> 5;            // row (32 chunks per row)
    const int chunk = blk & 31;
    const int tid   = threadIdx.x;
    const int v0    = chunk * 1024 + tid * 4;

    // Independent load, issued immediately.
    const float4 lv = *reinterpret_cast<const float4*>(logs + v0);

    // Dependent chain: idx -> h -> {backoff, pointers}.
    const int h = hist[(idx[0] - 1) * B_ + b];
    const float backoff = __ldg(logs + (size_t)X_ + G_ + h);

    // Prefetch override operands pre-barrier (independent of fill stores).
    bool  ov_do  = false;
    int   ov_tok = 0;
    float ov_lp  = 0.0f;
    if (tid < C_) {
        const int off = pointers[h];
        const int nc  = pointers[h + 1] - off + 1;
        if (tid < nc) {
            const int node = h + off + tid;           // bigram node id
            ov_tok = ids[node - U_];                  // child token id
            ov_lp  = logs[node];                      // bigram log-prob
            ov_do  = (ov_tok >> 10) == chunk;         // in this block's window
        }
    }

    // Fill store.
    float4 o;
    o.x = backoff + lv.x;
    o.y = backoff + lv.y;
    o.z = backoff + lv.z;
    o.w = backoff + lv.w;
    *reinterpret_cast<float4*>(out + (size_t)b * V_ + v0) = o;

    // Order fill stores before overrides within the block; override operands
    // are already in registers, so the post-barrier tail is one STG.
    __syncthreads();

    if (ov_do)
        out[(size_t)b * V_ + ov_tok] = ov_lp;
}

extern "C" void kernel_launch(void* const* d_in, const int* in_sizes, int n_in,
                              void* d_out, int out_size)
{
    const int*   hist     = (const int*)d_in[0];   // (S, B) int32
    const int*   idx      = (const int*)d_in[1];   // scalar int32
    const int*   pointers = (const int*)d_in[2];   // (X,) int32
    const int*   ids      = (const int*)d_in[3];   // (K,) int32
    const float* logs     = (const float*)d_in[4]; // (L,) float32
    float*       out      = (float*)d_out;         // (B, V) float32

    (void)in_sizes; (void)n_in; (void)out_size;

    llm_fused_kernel<<<(B_ * V_) / (256 * 4), 256>>>(hist, idx, pointers, ids, logs, out);
}

// round 9
// speedup vs baseline: 1.0435x; 1.0435x over previous
#include <cuda_runtime.h>
#include <cstddef>

// Problem constants (bigram trie, fixed shapes from reference)
#define V_  32768
#define C_  32
#define B_  32
#define K_  (V_ * C_)        // 1048576 bigram nodes
#define X_  (K_ + 1)         // pointers length
#define G_  V_               // unigram count
#define U_  (V_ + 1)         // first bigram node index

#define ROWS_PB 4            // rows (batch entries) per block
#define VCHUNK  1024         // v-span per block (256 threads * 4 floats)

// Fused fill + sparse override, row-group layout:
//  - grid = 32 v-chunks x 8 row-groups = 256 blocks (single wave)
//  - each thread loads logs[v0..v0+3] ONCE and writes it to 4 rows
//    (amortizes the unigram read 4x: total reads 1MB instead of 4MB)
//  - 4x32 override pairs prefetched pre-barrier; post-barrier = 1 predicated STG
__global__ void __launch_bounds__(256) llm_fused_kernel(
    const int* __restrict__ hist,
    const int* __restrict__ idx,
    const int* __restrict__ pointers,
    const int* __restrict__ ids,
    const float* __restrict__ logs,
    float* __restrict__ out)
{
    __shared__ float s_back[ROWS_PB];

    const int blk   = blockIdx.x;          // 0..255
    const int chunk = blk & 31;            // v-chunk
    const int b0    = (blk >> 5) * ROWS_PB;// first row of this block's group
    const int tid   = threadIdx.x;
    const int v0    = chunk * VCHUNK + tid * 4;

    // Independent load, issued immediately.
    const float4 lv   = *reinterpret_cast<const float4*>(logs + v0);
    const int    idxv = __ldg(idx);

    // Stage the 4 row backoffs into smem (threads 0..3).
    if (tid < ROWS_PB) {
        const int h = __ldg(hist + (idxv - 1) * B_ + b0 + tid);
        s_back[tid] = __ldg(logs + (size_t)X_ + G_ + h);
    }

    // Prefetch override operands pre-barrier: threads 0..127 own one (row, child) pair.
    bool  ov_do  = false;
    int   ov_r   = 0;
    int   ov_tok = 0;
    float ov_lp  = 0.0f;
    if (tid < ROWS_PB * C_) {
        ov_r = tid >> 5;                               // row within group (0..3)
        const int j = tid & 31;                        // child slot (0..31)
        const int h = __ldg(hist + (idxv - 1) * B_ + b0 + ov_r);
        const int off = __ldg(pointers + h);
        const int nc  = __ldg(pointers + h + 1) - off + 1;
        if (j < nc) {
            const int node = h + off + j;              // bigram node id
            ov_tok = __ldg(ids + (node - U_));         // child token id
            ov_lp  = __ldg(logs + node);               // bigram log-prob
            ov_do  = (ov_tok >> 10) == chunk;          // in this block's window
        }
    }

    __syncthreads();   // s_back ready

    // Fill: 4 rows per thread, one float4 store each.
    #pragma unroll
    for (int r = 0; r < ROWS_PB; r++) {
        const float bo = s_back[r];
        float4 o;
        o.x = bo + lv.x;
        o.y = bo + lv.y;
        o.z = bo + lv.z;
        o.w = bo + lv.w;
        *reinterpret_cast<float4*>(out + (size_t)(b0 + r) * V_ + v0) = o;
    }

    __syncthreads();   // fill stores before overrides

    if (ov_do)
        out[(size_t)(b0 + ov_r) * V_ + ov_tok] = ov_lp;
}

extern "C" void kernel_launch(void* const* d_in, const int* in_sizes, int n_in,
                              void* d_out, int out_size)
{
    const int*   hist     = (const int*)d_in[0];   // (S, B) int32
    const int*   idx      = (const int*)d_in[1];   // scalar int32
    const int*   pointers = (const int*)d_in[2];   // (X,) int32
    const int*   ids      = (const int*)d_in[3];   // (K,) int32
    const float* logs     = (const float*)d_in[4]; // (L,) float32
    float*       out      = (float*)d_out;         // (B, V) float32

    (void)in_sizes; (void)n_in; (void)out_size;

    // 32 v-chunks x (32/ROWS_PB)=8 row groups = 256 blocks
    llm_fused_kernel<<<(V_ / VCHUNK) * (B_ / ROWS_PB), 256>>>(
        hist, idx, pointers, ids, logs, out);
}